// round 2
// baseline (speedup 1.0000x reference)
#include <cuda_runtime.h>
#include <cuda_bf16.h>
#include <cstdint>

// GCN: 2 layers, N=100000 nodes, E=1.6M edges, 128 -> 128(relu) -> 64 -> softmax
// Pipeline (all fp32):
//   deg[dst] += 1 ; norm = rsqrt(deg+1)
//   h1s = (X @ W1) * norm[row]            (prescaled; agg1 tile zeroed here)
//   agg1[dst] += h1s[src]                 (atomic scatter)
//   a1 = relu((agg1 + h1s)*norm + b1)     (stored back into agg1)
//   h2s = (a1 @ W2) * norm[row]           (agg2 zeroed here)
//   agg2[dst] += h2s[src]
//   out = softmax((agg2 + h2s)*norm + b2)

#define GCN_N 100000
#define GCN_E 1600000
#define D_IN 128
#define D_HID 128
#define D_OUT 64

// scratch (static device allocations; allowed)
__device__ float g_deg[GCN_N];
__device__ float g_norm[GCN_N];
__device__ float g_h1[(size_t)GCN_N * D_HID];    // prescaled layer-1 transform
__device__ float g_agg1[(size_t)GCN_N * D_HID];  // layer-1 aggregate, then relu output
__device__ float g_h2[(size_t)GCN_N * D_OUT];
__device__ float g_agg2[(size_t)GCN_N * D_OUT];

// ---------------------------------------------------------------------------
__global__ void zero_kernel(float* __restrict__ p, int n) {
    int i = blockIdx.x * blockDim.x + threadIdx.x;
    if (i < n) p[i] = 0.f;
}

__global__ void deg_kernel(const int* __restrict__ dst, float* __restrict__ deg, int ne) {
    int e = blockIdx.x * blockDim.x + threadIdx.x;
    if (e < ne) atomicAdd(&deg[dst[e]], 1.0f);
}

__global__ void norm_kernel(const float* __restrict__ deg, float* __restrict__ nrm, int n) {
    int i = blockIdx.x * blockDim.x + threadIdx.x;
    if (i < n) nrm[i] = rsqrtf(deg[i] + 1.0f);
}

// ---------------------------------------------------------------------------
// Tiled fp32 GEMM: C[nrows, NC] = X[nrows,128] @ W[128,NC], scaled by norm[row].
// Also zeroes the matching Agg tile (so scatter's atomics start from 0).
// Block: 32 rows x NC cols, 256 threads (32 x 8); thread tile 4 rows x (NC/32) cols.
template <int NC>
__global__ __launch_bounds__(256) void gemm_kernel(
    const float* __restrict__ X, const float* __restrict__ W,
    const float* __restrict__ nrm, float* __restrict__ H,
    float* __restrict__ Agg, int nrows)
{
    constexpr int TN = NC / 32;
    __shared__ float Xs[32][128];
    __shared__ float Ws[32][NC];

    const int row0 = blockIdx.x * 32;
    const int tid = threadIdx.y * 32 + threadIdx.x;

    // load X tile (32 rows, full K=128)
    #pragma unroll
    for (int i = tid; i < 32 * 128; i += 256) {
        int r = i >> 7, k = i & 127;
        int gr = row0 + r;
        Xs[r][k] = (gr < nrows) ? X[(size_t)gr * 128 + k] : 0.f;
    }

    float acc[4][TN];
    #pragma unroll
    for (int i = 0; i < 4; i++)
        #pragma unroll
        for (int j = 0; j < TN; j++) acc[i][j] = 0.f;

    #pragma unroll
    for (int kc = 0; kc < 4; kc++) {
        __syncthreads();
        // load W k-slice [32 x NC]
        #pragma unroll
        for (int i = tid; i < 32 * NC; i += 256) {
            int kk = i / NC, c = i % NC;
            Ws[kk][c] = W[(size_t)(kc * 32 + kk) * NC + c];
        }
        __syncthreads();
        #pragma unroll
        for (int kk = 0; kk < 32; kk++) {
            float a[4], b[TN];
            #pragma unroll
            for (int i = 0; i < 4; i++) a[i] = Xs[threadIdx.y * 4 + i][kc * 32 + kk];
            #pragma unroll
            for (int j = 0; j < TN; j++) b[j] = Ws[kk][threadIdx.x + 32 * j];
            #pragma unroll
            for (int i = 0; i < 4; i++)
                #pragma unroll
                for (int j = 0; j < TN; j++) acc[i][j] = fmaf(a[i], b[j], acc[i][j]);
        }
    }

    #pragma unroll
    for (int i = 0; i < 4; i++) {
        int gr = row0 + threadIdx.y * 4 + i;
        if (gr < nrows) {
            float nv = nrm[gr];
            #pragma unroll
            for (int j = 0; j < TN; j++) {
                int c = threadIdx.x + 32 * j;
                H[(size_t)gr * NC + c] = acc[i][j] * nv;
                Agg[(size_t)gr * NC + c] = 0.f;
            }
        }
    }
}

// ---------------------------------------------------------------------------
// Edge scatter: Agg[dst] += H[src]  (vectorized load, 4 or 2 atomics per lane)
template <int NC>
__global__ __launch_bounds__(256) void scatter_kernel(
    const float* __restrict__ H, float* __restrict__ Agg,
    const int* __restrict__ src, const int* __restrict__ dst, int ne)
{
    int e = blockIdx.x * 8 + threadIdx.y;
    if (e >= ne) return;
    int s = src[e];
    int d = dst[e];
    constexpr int V = NC / 32;
    int c = threadIdx.x * V;
    const float* hp = H + (size_t)s * NC + c;
    float* ap = Agg + (size_t)d * NC + c;
    if (V == 4) {
        float4 v = *reinterpret_cast<const float4*>(hp);
        atomicAdd(ap + 0, v.x);
        atomicAdd(ap + 1, v.y);
        atomicAdd(ap + 2, v.z);
        atomicAdd(ap + 3, v.w);
    } else {
        float2 v = *reinterpret_cast<const float2*>(hp);
        atomicAdd(ap + 0, v.x);
        atomicAdd(ap + 1, v.y);
    }
}

// ---------------------------------------------------------------------------
// Layer-1 finalize: agg1 <- relu((agg1 + h1)*norm[row] + b1[col])
__global__ void finalize1_kernel(float* __restrict__ Agg, const float* __restrict__ H,
                                 const float* __restrict__ nrm, const float* __restrict__ b,
                                 int total)
{
    int idx = blockIdx.x * blockDim.x + threadIdx.x;
    if (idx >= total) return;
    int row = idx >> 7;  // D_HID = 128
    int col = idx & 127;
    float v = (Agg[idx] + H[idx]) * nrm[row] + b[col];
    Agg[idx] = fmaxf(v, 0.f);
}

// Layer-2 finalize + row softmax over 64 cols. One warp per row.
__global__ __launch_bounds__(256) void softmax_kernel(
    const float* __restrict__ Agg, const float* __restrict__ H,
    const float* __restrict__ nrm, const float* __restrict__ b,
    float* __restrict__ out, int nrows)
{
    int row = blockIdx.x * 8 + threadIdx.y;
    if (row >= nrows) return;
    int lane = threadIdx.x;
    float nv = nrm[row];
    size_t base = (size_t)row * 64;
    float v0 = (Agg[base + lane] + H[base + lane]) * nv + b[lane];
    float v1 = (Agg[base + lane + 32] + H[base + lane + 32]) * nv + b[lane + 32];
    float m = fmaxf(v0, v1);
    #pragma unroll
    for (int o = 16; o; o >>= 1) m = fmaxf(m, __shfl_xor_sync(0xffffffffu, m, o));
    float e0 = __expf(v0 - m);
    float e1 = __expf(v1 - m);
    float s = e0 + e1;
    #pragma unroll
    for (int o = 16; o; o >>= 1) s += __shfl_xor_sync(0xffffffffu, s, o);
    float inv = 1.0f / s;
    out[base + lane] = e0 * inv;
    out[base + lane + 32] = e1 * inv;
}

// ---------------------------------------------------------------------------
extern "C" void kernel_launch(void* const* d_in, const int* in_sizes, int n_in,
                              void* d_out, int out_size)
{
    const float* x = (const float*)d_in[0];
    const int* edge_index = (const int*)d_in[1];
    const float* W1 = (const float*)d_in[2];
    const float* b1 = (const float*)d_in[3];
    const float* W2 = (const float*)d_in[4];
    const float* b2 = (const float*)d_in[5];
    float* out = (float*)d_out;

    const int n = in_sizes[0] / D_IN;       // 100000
    const int ne = in_sizes[1] / 2;         // 1600000
    const int* src = edge_index;
    const int* dst = edge_index + ne;

    float *p_deg, *p_norm, *p_h1, *p_agg1, *p_h2, *p_agg2;
    cudaGetSymbolAddress((void**)&p_deg, g_deg);
    cudaGetSymbolAddress((void**)&p_norm, g_norm);
    cudaGetSymbolAddress((void**)&p_h1, g_h1);
    cudaGetSymbolAddress((void**)&p_agg1, g_agg1);
    cudaGetSymbolAddress((void**)&p_h2, g_h2);
    cudaGetSymbolAddress((void**)&p_agg2, g_agg2);

    // degrees + norm
    zero_kernel<<<(n + 255) / 256, 256>>>(p_deg, n);
    deg_kernel<<<(ne + 255) / 256, 256>>>(dst, p_deg, ne);
    norm_kernel<<<(n + 255) / 256, 256>>>(p_deg, p_norm, n);

    dim3 tb(32, 8);

    // layer 1
    gemm_kernel<D_HID><<<(n + 31) / 32, tb>>>(x, W1, p_norm, p_h1, p_agg1, n);
    scatter_kernel<D_HID><<<(ne + 7) / 8, tb>>>(p_h1, p_agg1, src, dst, ne);
    finalize1_kernel<<<(n * D_HID + 255) / 256, 256>>>(p_agg1, p_h1, p_norm, b1, n * D_HID);

    // layer 2
    gemm_kernel<D_OUT><<<(n + 31) / 32, tb>>>(p_agg1, W2, p_norm, p_h2, p_agg2, n);
    scatter_kernel<D_OUT><<<(ne + 7) / 8, tb>>>(p_h2, p_agg2, src, dst, ne);
    softmax_kernel<<<(n + 7) / 8, tb>>>(p_agg2, p_h2, p_norm, b2, out, n);
}

// round 4
// speedup vs baseline: 1.6784x; 1.6784x over previous
#include <cuda_runtime.h>
#include <cuda_bf16.h>
#include <cstdint>

// GCN 2-layer, N=100000, E=1.6M, 128 -> 128(relu) -> 64 -> softmax.
// R2: CSR(dst)-based gather aggregation (no feature atomics), fused epilogues,
//     64-row GEMM tiles with 8-row thread tiles.

#define GCN_N 100000
#define GCN_E 1600000
#define D_IN 128
#define D_HID 128
#define D_OUT 64

// static scratch
__device__ int   g_degi[GCN_N];
__device__ int   g_rowptr[GCN_N + 1];
__device__ int   g_cursor[GCN_N];
__device__ int   g_csr[GCN_E];
__device__ float g_norm[GCN_N];
__device__ float g_h1[(size_t)GCN_N * D_HID];   // prescaled layer-1 transform
__device__ float g_a1[(size_t)GCN_N * D_HID];   // relu output of layer 1
__device__ float g_h2[(size_t)GCN_N * D_OUT];   // prescaled layer-2 transform

// ---------------------------------------------------------------------------
__global__ void zero_int_kernel(int* __restrict__ p, int n) {
    int i = blockIdx.x * blockDim.x + threadIdx.x;
    if (i < n) p[i] = 0;
}

__global__ void deg_kernel(const int* __restrict__ dst, int* __restrict__ deg, int ne) {
    int e = blockIdx.x * blockDim.x + threadIdx.x;
    if (e < ne) atomicAdd(&deg[dst[e]], 1);
}

// norm = rsqrt(deg+1); single-block exclusive scan producing rowptr + cursor.
__global__ __launch_bounds__(1024) void scan_kernel(
    const int* __restrict__ deg, int* __restrict__ rowptr,
    int* __restrict__ cursor, float* __restrict__ nrm, int n)
{
    __shared__ int sums[1024];
    const int t = threadIdx.x;
    const int chunk = (n + 1023) / 1024;
    int begin = t * chunk;
    int end = begin + chunk; if (end > n) end = n;
    if (begin > n) begin = n;

    int s = 0;
    for (int i = begin; i < end; i++) s += deg[i];
    sums[t] = s;
    __syncthreads();
    // Hillis-Steele inclusive scan
    for (int d = 1; d < 1024; d <<= 1) {
        int v = (t >= d) ? sums[t - d] : 0;
        __syncthreads();
        sums[t] += v;
        __syncthreads();
    }
    int off = sums[t] - s;  // exclusive prefix
    for (int i = begin; i < end; i++) {
        rowptr[i] = off;
        cursor[i] = off;
        int dv = deg[i];
        nrm[i] = rsqrtf((float)dv + 1.0f);
        off += dv;
    }
    if (begin < end && end == n) rowptr[n] = off;
}

__global__ void fill_kernel(const int* __restrict__ src, const int* __restrict__ dst,
                            int* __restrict__ cursor, int* __restrict__ csr, int ne)
{
    int e = blockIdx.x * blockDim.x + threadIdx.x;
    if (e >= ne) return;
    int d = dst[e];
    int p = atomicAdd(&cursor[d], 1);
    csr[p] = src[e];
}

// ---------------------------------------------------------------------------
// GEMM: H[r, 0..NC) = (X[r,0..128) @ W) * nrm[r]
// block = 64 rows x NC cols, 256 threads (32,8), thread tile 8 x (NC/32)
template <int NC>
__global__ __launch_bounds__(256) void gemm_kernel(
    const float* __restrict__ X, const float* __restrict__ W,
    const float* __restrict__ nrm, float* __restrict__ H, int nrows)
{
    constexpr int TN = NC / 32;
    __shared__ float Xs[64 * 128];
    __shared__ float Ws[32 * NC];

    const int row0 = blockIdx.x * 64;
    const int tid = threadIdx.y * 32 + threadIdx.x;

    if (row0 + 64 <= nrows) {
        const float4* Xg = (const float4*)(X + (size_t)row0 * 128);
        float4* Xs4 = (float4*)Xs;
        #pragma unroll
        for (int i = 0; i < 8; i++) Xs4[tid + 256 * i] = Xg[tid + 256 * i];
    } else {
        for (int i = tid; i < 64 * 128; i += 256) {
            int r = i >> 7, k = i & 127;
            int gr = row0 + r;
            Xs[i] = (gr < nrows) ? X[(size_t)gr * 128 + k] : 0.f;
        }
    }

    float acc[8][TN];
    #pragma unroll
    for (int i = 0; i < 8; i++)
        #pragma unroll
        for (int j = 0; j < TN; j++) acc[i][j] = 0.f;

    #pragma unroll
    for (int kc = 0; kc < 4; kc++) {
        __syncthreads();
        #pragma unroll
        for (int i = tid; i < 32 * NC; i += 256) {
            int kk = i / NC, c = i % NC;
            Ws[i] = W[(size_t)(kc * 32 + kk) * NC + c];
        }
        __syncthreads();
        #pragma unroll
        for (int kk = 0; kk < 32; kk++) {
            float a[8], b[TN];
            #pragma unroll
            for (int i = 0; i < 8; i++) a[i] = Xs[(threadIdx.y * 8 + i) * 128 + kc * 32 + kk];
            #pragma unroll
            for (int j = 0; j < TN; j++) b[j] = Ws[kk * NC + threadIdx.x + 32 * j];
            #pragma unroll
            for (int i = 0; i < 8; i++)
                #pragma unroll
                for (int j = 0; j < TN; j++) acc[i][j] = fmaf(a[i], b[j], acc[i][j]);
        }
    }

    #pragma unroll
    for (int i = 0; i < 8; i++) {
        int gr = row0 + threadIdx.y * 8 + i;
        if (gr < nrows) {
            float nv = nrm[gr];
            #pragma unroll
            for (int j = 0; j < TN; j++)
                H[(size_t)gr * NC + threadIdx.x + 32 * j] = acc[i][j] * nv;
        }
    }
}

// ---------------------------------------------------------------------------
// Layer-1 aggregate + finalize: a1[v] = relu((h1[v] + sum_{u in N(v)} h1[u]) * nrm[v] + b1)
// One warp per node, float4 per lane (128 cols).
__global__ __launch_bounds__(256) void agg1_kernel(
    const float* __restrict__ h1, const int* __restrict__ csr,
    const int* __restrict__ rowptr, const float* __restrict__ nrm,
    const float* __restrict__ b1, float* __restrict__ a1, int n)
{
    int node = blockIdx.x * 8 + threadIdx.y;
    if (node >= n) return;
    int lane = threadIdx.x;
    const float4* H4 = (const float4*)h1;

    float4 acc0 = H4[(size_t)node * 32 + lane];  // self contribution
    float4 acc1 = make_float4(0.f, 0.f, 0.f, 0.f);
    int beg = rowptr[node], end = rowptr[node + 1];
    int j = beg;
    for (; j + 1 < end; j += 2) {
        int s0 = csr[j], s1 = csr[j + 1];
        float4 v0 = H4[(size_t)s0 * 32 + lane];
        float4 v1 = H4[(size_t)s1 * 32 + lane];
        acc0.x += v0.x; acc0.y += v0.y; acc0.z += v0.z; acc0.w += v0.w;
        acc1.x += v1.x; acc1.y += v1.y; acc1.z += v1.z; acc1.w += v1.w;
    }
    if (j < end) {
        float4 v = H4[(size_t)csr[j] * 32 + lane];
        acc0.x += v.x; acc0.y += v.y; acc0.z += v.z; acc0.w += v.w;
    }
    float nv = nrm[node];
    float4 bb = ((const float4*)b1)[lane];
    float4 r;
    r.x = fmaxf(fmaf(acc0.x + acc1.x, nv, bb.x), 0.f);
    r.y = fmaxf(fmaf(acc0.y + acc1.y, nv, bb.y), 0.f);
    r.z = fmaxf(fmaf(acc0.z + acc1.z, nv, bb.z), 0.f);
    r.w = fmaxf(fmaf(acc0.w + acc1.w, nv, bb.w), 0.f);
    ((float4*)a1)[(size_t)node * 32 + lane] = r;
}

// Layer-2 aggregate + softmax fused. One warp per node, float2 per lane (64 cols).
__global__ __launch_bounds__(256) void agg2_kernel(
    const float* __restrict__ h2, const int* __restrict__ csr,
    const int* __restrict__ rowptr, const float* __restrict__ nrm,
    const float* __restrict__ b2, float* __restrict__ out, int n)
{
    int node = blockIdx.x * 8 + threadIdx.y;
    if (node >= n) return;
    int lane = threadIdx.x;
    const float2* H2 = (const float2*)h2;

    float2 acc0 = H2[(size_t)node * 32 + lane];  // self
    float2 acc1 = make_float2(0.f, 0.f);
    int beg = rowptr[node], end = rowptr[node + 1];
    int j = beg;
    for (; j + 1 < end; j += 2) {
        int s0 = csr[j], s1 = csr[j + 1];
        float2 v0 = H2[(size_t)s0 * 32 + lane];
        float2 v1 = H2[(size_t)s1 * 32 + lane];
        acc0.x += v0.x; acc0.y += v0.y;
        acc1.x += v1.x; acc1.y += v1.y;
    }
    if (j < end) {
        float2 v = H2[(size_t)csr[j] * 32 + lane];
        acc0.x += v.x; acc0.y += v.y;
    }
    float nv = nrm[node];
    float2 bb = ((const float2*)b2)[lane];
    float vx = fmaf(acc0.x + acc1.x, nv, bb.x);
    float vy = fmaf(acc0.y + acc1.y, nv, bb.y);

    float m = fmaxf(vx, vy);
    #pragma unroll
    for (int o = 16; o; o >>= 1) m = fmaxf(m, __shfl_xor_sync(0xffffffffu, m, o));
    float ex = __expf(vx - m);
    float ey = __expf(vy - m);
    float s = ex + ey;
    #pragma unroll
    for (int o = 16; o; o >>= 1) s += __shfl_xor_sync(0xffffffffu, s, o);
    float inv = 1.0f / s;
    float2 r;
    r.x = ex * inv;
    r.y = ey * inv;
    ((float2*)out)[(size_t)node * 32 + lane] = r;
}

// ---------------------------------------------------------------------------
extern "C" void kernel_launch(void* const* d_in, const int* in_sizes, int n_in,
                              void* d_out, int out_size)
{
    const float* x = (const float*)d_in[0];
    const int* edge_index = (const int*)d_in[1];
    const float* W1 = (const float*)d_in[2];
    const float* b1 = (const float*)d_in[3];
    const float* W2 = (const float*)d_in[4];
    const float* b2 = (const float*)d_in[5];
    float* out = (float*)d_out;

    const int n = in_sizes[0] / D_IN;
    const int ne = in_sizes[1] / 2;
    const int* src = edge_index;
    const int* dst = edge_index + ne;

    int *p_degi, *p_rowptr, *p_cursor, *p_csr;
    float *p_norm, *p_h1, *p_a1, *p_h2;
    cudaGetSymbolAddress((void**)&p_degi, g_degi);
    cudaGetSymbolAddress((void**)&p_rowptr, g_rowptr);
    cudaGetSymbolAddress((void**)&p_cursor, g_cursor);
    cudaGetSymbolAddress((void**)&p_csr, g_csr);
    cudaGetSymbolAddress((void**)&p_norm, g_norm);
    cudaGetSymbolAddress((void**)&p_h1, g_h1);
    cudaGetSymbolAddress((void**)&p_a1, g_a1);
    cudaGetSymbolAddress((void**)&p_h2, g_h2);

    // CSR build + norm
    zero_int_kernel<<<(n + 255) / 256, 256>>>(p_degi, n);
    deg_kernel<<<(ne + 255) / 256, 256>>>(dst, p_degi, ne);
    scan_kernel<<<1, 1024>>>(p_degi, p_rowptr, p_cursor, p_norm, n);
    fill_kernel<<<(ne + 255) / 256, 256>>>(src, dst, p_cursor, p_csr, ne);

    dim3 tb(32, 8);

    // layer 1 (GEMM overlaps nothing but is independent of CSR build; stream order fine)
    gemm_kernel<D_HID><<<(n + 63) / 64, tb>>>(x, W1, p_norm, p_h1, n);
    agg1_kernel<<<(n + 7) / 8, tb>>>(p_h1, p_csr, p_rowptr, p_norm, b1, p_a1, n);

    // layer 2
    gemm_kernel<D_OUT><<<(n + 63) / 64, tb>>>(p_a1, W2, p_norm, p_h2, n);
    agg2_kernel<<<(n + 7) / 8, tb>>>(p_h2, p_csr, p_rowptr, p_norm, b2, out, n);
}

// round 5
// speedup vs baseline: 1.6961x; 1.0106x over previous
#include <cuda_runtime.h>
#include <cuda_bf16.h>
#include <cstdint>

// GCN 2-layer, N=100000, E=1.6M, 128 -> 128(relu) -> 64 -> softmax.
// R4: f32x2 packed-FMA GEMM, norm folded into aggregation FMA (GEMM no longer
//     depends on CSR chain -> CSR build overlapped on side stream), 4-way MLP
//     unrolled gather aggregation, ILP-4 deg/fill.

#define GCN_N 100000
#define GCN_E 1600000
#define D_IN 128
#define D_HID 128
#define D_OUT 64

// static scratch
__device__ int   g_degi[GCN_N];
__device__ int   g_rowptr[GCN_N + 1];
__device__ int   g_cursor[GCN_N];
__device__ int   g_csr[GCN_E];
__device__ float g_norm[GCN_N];
__device__ float g_h1[(size_t)GCN_N * D_HID];   // raw X@W1
__device__ float g_a1[(size_t)GCN_N * D_HID];   // relu output of layer 1
__device__ float g_h2[(size_t)GCN_N * D_OUT];   // raw a1@W2

// ---------------------------------------------------------------------------
__global__ void zero_int_kernel(int* __restrict__ p, int n) {
    int i = blockIdx.x * blockDim.x + threadIdx.x;
    if (i < n) p[i] = 0;
}

// ILP-4 degree histogram (int4 loads, 4 independent atomics)
__global__ void deg_kernel(const int* __restrict__ dst, int* __restrict__ deg, int ne) {
    int t = blockIdx.x * blockDim.x + threadIdx.x;
    int ne4 = ne >> 2;
    if (t < ne4) {
        int4 d = ((const int4*)dst)[t];
        atomicAdd(&deg[d.x], 1);
        atomicAdd(&deg[d.y], 1);
        atomicAdd(&deg[d.z], 1);
        atomicAdd(&deg[d.w], 1);
    }
    int rem = ne - ne4 * 4;
    if (t < rem) atomicAdd(&deg[dst[ne4 * 4 + t]], 1);
}

// norm = rsqrt(deg+1); single-block exclusive scan producing rowptr + cursor.
__global__ __launch_bounds__(1024) void scan_kernel(
    const int* __restrict__ deg, int* __restrict__ rowptr,
    int* __restrict__ cursor, float* __restrict__ nrm, int n)
{
    __shared__ int sums[1024];
    const int t = threadIdx.x;
    const int chunk = (n + 1023) / 1024;
    int begin = t * chunk;
    int end = begin + chunk; if (end > n) end = n;
    if (begin > n) begin = n;

    int s = 0;
    for (int i = begin; i < end; i++) s += deg[i];
    sums[t] = s;
    __syncthreads();
    for (int d = 1; d < 1024; d <<= 1) {
        int v = (t >= d) ? sums[t - d] : 0;
        __syncthreads();
        sums[t] += v;
        __syncthreads();
    }
    int off = sums[t] - s;  // exclusive prefix
    for (int i = begin; i < end; i++) {
        rowptr[i] = off;
        cursor[i] = off;
        int dv = deg[i];
        nrm[i] = rsqrtf((float)dv + 1.0f);
        off += dv;
    }
    if (begin < end && end == n) rowptr[n] = off;
}

// ILP-4 CSR fill
__global__ void fill_kernel(const int* __restrict__ src, const int* __restrict__ dst,
                            int* __restrict__ cursor, int* __restrict__ csr, int ne)
{
    int t = blockIdx.x * blockDim.x + threadIdx.x;
    int ne4 = ne >> 2;
    if (t < ne4) {
        int4 s = ((const int4*)src)[t];
        int4 d = ((const int4*)dst)[t];
        int p0 = atomicAdd(&cursor[d.x], 1);
        int p1 = atomicAdd(&cursor[d.y], 1);
        int p2 = atomicAdd(&cursor[d.z], 1);
        int p3 = atomicAdd(&cursor[d.w], 1);
        csr[p0] = s.x; csr[p1] = s.y; csr[p2] = s.z; csr[p3] = s.w;
    }
    int rem = ne - ne4 * 4;
    if (t < rem) {
        int e = ne4 * 4 + t;
        int p = atomicAdd(&cursor[dst[e]], 1);
        csr[p] = src[e];
    }
}

// ---------------------------------------------------------------------------
// GEMM with packed f32x2 FMA: H[r, 0..NC) = X[r,0..128) @ W  (no norm scale)
// block = 64 rows x NC cols, 256 threads (32,8); thread: 8 rows x TN cols.
// Ws staged pair-interleaved: Ws[kk*NC + tx*TN + j] = W[k][tx + 32*j]
template <int NC>
__global__ __launch_bounds__(256) void gemm_kernel(
    const float* __restrict__ X, const float* __restrict__ W,
    float* __restrict__ H, int nrows)
{
    constexpr int TN = NC / 32;   // 4 or 2
    constexpr int TP = TN / 2;    // packed pairs per thread: 2 or 1
    __shared__ __align__(16) float Xs[64 * 128];
    __shared__ __align__(16) float Ws[32 * NC];

    const int row0 = blockIdx.x * 64;
    const int tid = threadIdx.y * 32 + threadIdx.x;
    const int tx = threadIdx.x;

    if (row0 + 64 <= nrows) {
        const float4* Xg = (const float4*)(X + (size_t)row0 * 128);
        float4* Xs4 = (float4*)Xs;
        #pragma unroll
        for (int i = 0; i < 8; i++) Xs4[tid + 256 * i] = Xg[tid + 256 * i];
    } else {
        for (int i = tid; i < 64 * 128; i += 256) {
            int gr = row0 + (i >> 7);
            Xs[i] = (gr < nrows) ? X[(size_t)gr * 128 + (i & 127)] : 0.f;
        }
    }

    unsigned long long accP[8][TP];
    #pragma unroll
    for (int i = 0; i < 8; i++)
        #pragma unroll
        for (int p = 0; p < TP; p++) accP[i][p] = 0ull;

    #pragma unroll
    for (int kc = 0; kc < 4; kc++) {
        __syncthreads();
        for (int i = tid; i < 32 * NC; i += 256) {
            int kk = i / NC, c = i % NC;
            Ws[kk * NC + (c & 31) * TN + (c >> 5)] = W[(size_t)(kc * 32 + kk) * NC + c];
        }
        __syncthreads();
        #pragma unroll
        for (int kk = 0; kk < 32; kk++) {
            unsigned long long bP[TP];
            if (TP == 2) {
                ulonglong2 t2 = *reinterpret_cast<const ulonglong2*>(&Ws[kk * NC + tx * 4]);
                bP[0] = t2.x; bP[1] = t2.y;
            } else {
                bP[0] = *reinterpret_cast<const unsigned long long*>(&Ws[kk * NC + tx * 2]);
            }
            #pragma unroll
            for (int i = 0; i < 8; i++) {
                unsigned int au = __float_as_uint(Xs[(threadIdx.y * 8 + i) * 128 + kc * 32 + kk]);
                unsigned long long aP;
                asm("mov.b64 %0, {%1, %1};" : "=l"(aP) : "r"(au));
                #pragma unroll
                for (int p = 0; p < TP; p++)
                    asm("fma.rn.f32x2 %0, %1, %2, %0;" : "+l"(accP[i][p]) : "l"(aP), "l"(bP[p]));
            }
        }
    }

    #pragma unroll
    for (int i = 0; i < 8; i++) {
        int gr = row0 + threadIdx.y * 8 + i;
        if (gr < nrows) {
            #pragma unroll
            for (int p = 0; p < TP; p++) {
                unsigned int lo_u, hi_u;
                asm("mov.b64 {%0, %1}, %2;" : "=r"(lo_u), "=r"(hi_u) : "l"(accP[i][p]));
                H[(size_t)gr * NC + tx + 64 * p]      = __uint_as_float(lo_u);
                H[(size_t)gr * NC + tx + 32 + 64 * p] = __uint_as_float(hi_u);
            }
        }
    }
}

// ---------------------------------------------------------------------------
// Layer-1 aggregate + finalize:
//   a1[v] = relu( nrm[v] * ( h1[v]*nrm[v] + sum_u h1[u]*nrm[u] ) + b1 )
// One warp per node, float4 per lane (128 cols), 4-way MLP unroll.
__global__ __launch_bounds__(256) void agg1_kernel(
    const float* __restrict__ h1, const int* __restrict__ csr,
    const int* __restrict__ rowptr, const float* __restrict__ nrm,
    const float* __restrict__ b1, float* __restrict__ a1, int n)
{
    int node = blockIdx.x * 8 + threadIdx.y;
    if (node >= n) return;
    int lane = threadIdx.x;
    const float4* H4 = (const float4*)h1;

    float nself = nrm[node];
    float4 sv = H4[(size_t)node * 32 + lane];
    float4 acc0, acc1, acc2, acc3;
    acc0.x = sv.x * nself; acc0.y = sv.y * nself;
    acc0.z = sv.z * nself; acc0.w = sv.w * nself;
    acc1 = make_float4(0.f, 0.f, 0.f, 0.f);
    acc2 = make_float4(0.f, 0.f, 0.f, 0.f);
    acc3 = make_float4(0.f, 0.f, 0.f, 0.f);

    int beg = rowptr[node], end = rowptr[node + 1];
    int j = beg;
    for (; j + 4 <= end; j += 4) {
        int s0 = csr[j], s1 = csr[j + 1], s2 = csr[j + 2], s3 = csr[j + 3];
        float n0 = nrm[s0], n1 = nrm[s1], n2 = nrm[s2], n3 = nrm[s3];
        float4 v0 = H4[(size_t)s0 * 32 + lane];
        float4 v1 = H4[(size_t)s1 * 32 + lane];
        float4 v2 = H4[(size_t)s2 * 32 + lane];
        float4 v3 = H4[(size_t)s3 * 32 + lane];
        acc0.x = fmaf(v0.x, n0, acc0.x); acc0.y = fmaf(v0.y, n0, acc0.y);
        acc0.z = fmaf(v0.z, n0, acc0.z); acc0.w = fmaf(v0.w, n0, acc0.w);
        acc1.x = fmaf(v1.x, n1, acc1.x); acc1.y = fmaf(v1.y, n1, acc1.y);
        acc1.z = fmaf(v1.z, n1, acc1.z); acc1.w = fmaf(v1.w, n1, acc1.w);
        acc2.x = fmaf(v2.x, n2, acc2.x); acc2.y = fmaf(v2.y, n2, acc2.y);
        acc2.z = fmaf(v2.z, n2, acc2.z); acc2.w = fmaf(v2.w, n2, acc2.w);
        acc3.x = fmaf(v3.x, n3, acc3.x); acc3.y = fmaf(v3.y, n3, acc3.y);
        acc3.z = fmaf(v3.z, n3, acc3.z); acc3.w = fmaf(v3.w, n3, acc3.w);
    }
    for (; j < end; j++) {
        int s = csr[j];
        float nn = nrm[s];
        float4 v = H4[(size_t)s * 32 + lane];
        acc0.x = fmaf(v.x, nn, acc0.x); acc0.y = fmaf(v.y, nn, acc0.y);
        acc0.z = fmaf(v.z, nn, acc0.z); acc0.w = fmaf(v.w, nn, acc0.w);
    }
    float sx = (acc0.x + acc1.x) + (acc2.x + acc3.x);
    float sy = (acc0.y + acc1.y) + (acc2.y + acc3.y);
    float sz = (acc0.z + acc1.z) + (acc2.z + acc3.z);
    float sw = (acc0.w + acc1.w) + (acc2.w + acc3.w);
    float4 bb = ((const float4*)b1)[lane];
    float4 r;
    r.x = fmaxf(fmaf(sx, nself, bb.x), 0.f);
    r.y = fmaxf(fmaf(sy, nself, bb.y), 0.f);
    r.z = fmaxf(fmaf(sz, nself, bb.z), 0.f);
    r.w = fmaxf(fmaf(sw, nself, bb.w), 0.f);
    ((float4*)a1)[(size_t)node * 32 + lane] = r;
}

// Layer-2 aggregate + softmax fused. One warp per node, float2 per lane (64 cols).
__global__ __launch_bounds__(256) void agg2_kernel(
    const float* __restrict__ h2, const int* __restrict__ csr,
    const int* __restrict__ rowptr, const float* __restrict__ nrm,
    const float* __restrict__ b2, float* __restrict__ out, int n)
{
    int node = blockIdx.x * 8 + threadIdx.y;
    if (node >= n) return;
    int lane = threadIdx.x;
    const float2* H2 = (const float2*)h2;

    float nself = nrm[node];
    float2 sv = H2[(size_t)node * 32 + lane];
    float2 acc0, acc1, acc2, acc3;
    acc0.x = sv.x * nself; acc0.y = sv.y * nself;
    acc1 = make_float2(0.f, 0.f);
    acc2 = make_float2(0.f, 0.f);
    acc3 = make_float2(0.f, 0.f);

    int beg = rowptr[node], end = rowptr[node + 1];
    int j = beg;
    for (; j + 4 <= end; j += 4) {
        int s0 = csr[j], s1 = csr[j + 1], s2 = csr[j + 2], s3 = csr[j + 3];
        float n0 = nrm[s0], n1 = nrm[s1], n2 = nrm[s2], n3 = nrm[s3];
        float2 v0 = H2[(size_t)s0 * 32 + lane];
        float2 v1 = H2[(size_t)s1 * 32 + lane];
        float2 v2 = H2[(size_t)s2 * 32 + lane];
        float2 v3 = H2[(size_t)s3 * 32 + lane];
        acc0.x = fmaf(v0.x, n0, acc0.x); acc0.y = fmaf(v0.y, n0, acc0.y);
        acc1.x = fmaf(v1.x, n1, acc1.x); acc1.y = fmaf(v1.y, n1, acc1.y);
        acc2.x = fmaf(v2.x, n2, acc2.x); acc2.y = fmaf(v2.y, n2, acc2.y);
        acc3.x = fmaf(v3.x, n3, acc3.x); acc3.y = fmaf(v3.y, n3, acc3.y);
    }
    for (; j < end; j++) {
        int s = csr[j];
        float nn = nrm[s];
        float2 v = H2[(size_t)s * 32 + lane];
        acc0.x = fmaf(v.x, nn, acc0.x); acc0.y = fmaf(v.y, nn, acc0.y);
    }
    float2 bb = ((const float2*)b2)[lane];
    float vx = fmaf((acc0.x + acc1.x) + (acc2.x + acc3.x), nself, bb.x);
    float vy = fmaf((acc0.y + acc1.y) + (acc2.y + acc3.y), nself, bb.y);

    float m = fmaxf(vx, vy);
    #pragma unroll
    for (int o = 16; o; o >>= 1) m = fmaxf(m, __shfl_xor_sync(0xffffffffu, m, o));
    float ex = __expf(vx - m);
    float ey = __expf(vy - m);
    float s = ex + ey;
    #pragma unroll
    for (int o = 16; o; o >>= 1) s += __shfl_xor_sync(0xffffffffu, s, o);
    float inv = 1.0f / s;
    float2 r;
    r.x = ex * inv;
    r.y = ey * inv;
    ((float2*)out)[(size_t)node * 32 + lane] = r;
}

// ---------------------------------------------------------------------------
static cudaStream_t g_side = nullptr;
static cudaEvent_t g_evFork = nullptr;
static cudaEvent_t g_evJoin = nullptr;

extern "C" void kernel_launch(void* const* d_in, const int* in_sizes, int n_in,
                              void* d_out, int out_size)
{
    const float* x = (const float*)d_in[0];
    const int* edge_index = (const int*)d_in[1];
    const float* W1 = (const float*)d_in[2];
    const float* b1 = (const float*)d_in[3];
    const float* W2 = (const float*)d_in[4];
    const float* b2 = (const float*)d_in[5];
    float* out = (float*)d_out;

    const int n = in_sizes[0] / D_IN;
    const int ne = in_sizes[1] / 2;
    const int* src = edge_index;
    const int* dst = edge_index + ne;

    int *p_degi, *p_rowptr, *p_cursor, *p_csr;
    float *p_norm, *p_h1, *p_a1, *p_h2;
    cudaGetSymbolAddress((void**)&p_degi, g_degi);
    cudaGetSymbolAddress((void**)&p_rowptr, g_rowptr);
    cudaGetSymbolAddress((void**)&p_cursor, g_cursor);
    cudaGetSymbolAddress((void**)&p_csr, g_csr);
    cudaGetSymbolAddress((void**)&p_norm, g_norm);
    cudaGetSymbolAddress((void**)&p_h1, g_h1);
    cudaGetSymbolAddress((void**)&p_a1, g_a1);
    cudaGetSymbolAddress((void**)&p_h2, g_h2);

    if (g_side == nullptr) {
        cudaStreamCreateWithFlags(&g_side, cudaStreamNonBlocking);
        cudaEventCreateWithFlags(&g_evFork, cudaEventDisableTiming);
        cudaEventCreateWithFlags(&g_evJoin, cudaEventDisableTiming);
    }

    dim3 tb(32, 8);
    const int ne4 = ne / 4;

    // Fork: CSR build chain on side stream, gemm1 on main stream (independent).
    cudaEventRecord(g_evFork, 0);
    cudaStreamWaitEvent(g_side, g_evFork, 0);

    zero_int_kernel<<<(n + 255) / 256, 256, 0, g_side>>>(p_degi, n);
    deg_kernel<<<(ne4 + 255) / 256, 256, 0, g_side>>>(dst, p_degi, ne);
    scan_kernel<<<1, 1024, 0, g_side>>>(p_degi, p_rowptr, p_cursor, p_norm, n);
    fill_kernel<<<(ne4 + 255) / 256, 256, 0, g_side>>>(src, dst, p_cursor, p_csr, ne);
    cudaEventRecord(g_evJoin, g_side);

    gemm_kernel<D_HID><<<(n + 63) / 64, tb>>>(x, W1, p_h1, n);

    // Join: aggregation needs both h1 and the CSR.
    cudaStreamWaitEvent(0, g_evJoin, 0);

    agg1_kernel<<<(n + 7) / 8, tb>>>(p_h1, p_csr, p_rowptr, p_norm, b1, p_a1, n);
    gemm_kernel<D_OUT><<<(n + 63) / 64, tb>>>(p_a1, W2, p_h2, n);
    agg2_kernel<<<(n + 7) / 8, tb>>>(p_h2, p_csr, p_rowptr, p_norm, b2, out, n);
}